// round 2
// baseline (speedup 1.0000x reference)
#include <cuda_runtime.h>

#define N_NODES 16384
#define N_EDGES 262144

// Scratch (static device globals — no allocation at runtime)
__device__ float g_up[N_NODES * 128];   // per node: [s1(32), v1x(32), v1y(32), v1z(32)]
__device__ int   g_cnt[N_NODES];
__device__ int   g_off[N_NODES + 1];
__device__ int   g_cursor[N_NODES];
__device__ int   g_perm[N_EDGES];

__device__ __forceinline__ float silu_f(float x) {
    return x / (1.0f + __expf(-x));
}

// ---------------------------------------------------------------------------
// CSR build: histogram -> scan -> scatter
// ---------------------------------------------------------------------------
__global__ void zero_cnt_kernel() {
    int i = blockIdx.x * blockDim.x + threadIdx.x;   // 32*512 = 16384
    g_cnt[i] = 0;
}

__global__ void hist_kernel(const int* __restrict__ receivers) {
    int e = blockIdx.x * blockDim.x + threadIdx.x;   // 512*512 = 262144
    atomicAdd(&g_cnt[receivers[e]], 1);
}

__global__ void scan_kernel() {
    __shared__ int sPart[512];
    int t = threadIdx.x;
    int base = t * 32;
    int loc[32];
    int s = 0;
    #pragma unroll
    for (int j = 0; j < 32; j++) { loc[j] = s; s += g_cnt[base + j]; }
    sPart[t] = s;
    __syncthreads();
    // Hillis-Steele inclusive scan over 512 partials
    #pragma unroll
    for (int off = 1; off < 512; off <<= 1) {
        int v = (t >= off) ? sPart[t - off] : 0;
        __syncthreads();
        sPart[t] += v;
        __syncthreads();
    }
    int prefix = (t == 0) ? 0 : sPart[t - 1];
    #pragma unroll
    for (int j = 0; j < 32; j++) {
        int o = prefix + loc[j];
        g_off[base + j] = o;
        g_cursor[base + j] = o;
    }
    if (t == 511) g_off[N_NODES] = prefix + s;
}

__global__ void scatter_kernel(const int* __restrict__ receivers) {
    int e = blockIdx.x * blockDim.x + threadIdx.x;
    int p = atomicAdd(&g_cursor[receivers[e]], 1);
    g_perm[p] = e;
}

// ---------------------------------------------------------------------------
// Node up-projection (unchanged from passing baseline)
// ---------------------------------------------------------------------------
__global__ void up_kernel(const float* __restrict__ nf,
                          const float* __restrict__ Wus,
                          const float* __restrict__ Wuv) {
    __shared__ float sWs[1024];
    __shared__ float sWv[1024];
    __shared__ float sIn[128];
    int t = threadIdx.x;
    for (int i = t; i < 1024; i += 128) { sWs[i] = Wus[i]; sWv[i] = Wuv[i]; }
    __syncthreads();
    int k = t & 31, sec = t >> 5;
    for (int n = blockIdx.x; n < N_NODES; n += gridDim.x) {
        sIn[t] = nf[n * 128 + t];
        __syncthreads();
        float acc = 0.f;
        if (sec == 0) {
            #pragma unroll 8
            for (int m = 0; m < 32; m++) acc = fmaf(sIn[m], sWs[m * 32 + k], acc);
        } else {
            int i = sec - 1;
            #pragma unroll 8
            for (int m = 0; m < 32; m++) acc = fmaf(sIn[32 + m * 3 + i], sWv[m * 32 + k], acc);
        }
        g_up[(size_t)n * 128 + t] = acc * 0.17677669529663687f;  // 32^-0.5
        __syncthreads();
    }
}

// ---------------------------------------------------------------------------
// Fused gather + message + down-projection + skip + gating.
// One warp per node; no atomics, no g_acc round-trip.
// ---------------------------------------------------------------------------
__global__ void __launch_bounds__(256)
fused_node_kernel(const float* __restrict__ nf,
                  const float* __restrict__ edge_sh,
                  const float* __restrict__ radial,
                  const float* __restrict__ W_r1,
                  const float* __restrict__ W_r2,
                  const float* __restrict__ W_dn_s,
                  const float* __restrict__ W_dn_v,
                  const float* __restrict__ W_sk_s,
                  const float* __restrict__ W_sk_v,
                  const int* __restrict__ senders,
                  const int* __restrict__ species,
                  float* __restrict__ out) {
    __shared__ float sW1[64];
    __shared__ float sW2[1024];
    __shared__ float sWs[64 * 64];
    __shared__ float sWv[64 * 32];
    __shared__ __align__(16) float sStage[8][384];
    int t = threadIdx.x;
    if (t < 64) sW1[t] = W_r1[t];
    for (int i = t; i < 1024; i += 256) sW2[i] = W_r2[i];
    for (int i = t; i < 4096; i += 256) sWs[i] = W_dn_s[i];
    for (int i = t; i < 2048; i += 256) sWv[i] = W_dn_v[i];
    __syncthreads();

    int warp = t >> 5, lane = t & 31;
    int j8 = lane & 7;
    int n = blockIdx.x * 8 + warp;

    const float INV_SQRT8 = 0.3535533905932738f;
    const float SC = INV_SQRT8 * 0.25f;   // radial scale * AVG_NEIGH^-0.5

    // message accumulators: S(64), V0(64), V1(64), V2(64) split low/high half
    float aS0 = 0.f, aS1 = 0.f;
    float aV0l = 0.f, aV0h = 0.f;
    float aV1l = 0.f, aV1h = 0.f;
    float aV2l = 0.f, aV2h = 0.f;

    int beg = g_off[n];
    int end = g_off[n + 1];

    for (int p = beg; p < end; p++) {
        int e = g_perm[p];
        int snd = senders[e];

        // radial MLP: lanes 0..7 hold r; all lanes compute h for j = lane&7
        float r = (lane < 8) ? radial[e * 8 + lane] : 0.f;
        float pre = 0.f;
        #pragma unroll
        for (int k = 0; k < 8; k++) {
            float rk = __shfl_sync(0xffffffffu, r, k);
            pre = fmaf(rk, sW1[k * 8 + j8], pre);
        }
        float h = silu_f(pre * INV_SQRT8);

        // w = h @ W_r2 : lane m gets w_ss, w_vs, w_vt, w_st
        float w0 = 0.f, w1 = 0.f, w2 = 0.f, w3 = 0.f;
        #pragma unroll
        for (int j = 0; j < 8; j++) {
            float hj = __shfl_sync(0xffffffffu, h, j);
            w0 = fmaf(hj, sW2[j * 128 + lane], w0);
            w1 = fmaf(hj, sW2[j * 128 + 32 + lane], w1);
            w2 = fmaf(hj, sW2[j * 128 + 64 + lane], w2);
            w3 = fmaf(hj, sW2[j * 128 + 96 + lane], w3);
        }
        w0 *= SC; w1 *= SC; w2 *= SC; w3 *= SC;

        // gather sender up-features (L2-resident)
        const float* up = g_up + (size_t)snd * 128;
        float ss  = up[lane];
        float vs0 = up[32 + lane];
        float vs1 = up[64 + lane];
        float vs2 = up[96 + lane];
        float4 y = ((const float4*)edge_sh)[e];   // y.y, y.z, y.w are l=1 sh

        float dot = (vs0 * y.y + vs1 * y.z + vs2 * y.w) * 0.5773502691896258f;
        float sst = ss * w2;

        aS0  = fmaf(ss,  w0, aS0);
        aS1  = fmaf(dot, w3, aS1);
        aV0l = fmaf(vs0, w1, aV0l);  aV0h = fmaf(sst, y.y, aV0h);
        aV1l = fmaf(vs1, w1, aV1l);  aV1h = fmaf(sst, y.z, aV1h);
        aV2l = fmaf(vs2, w1, aV2l);  aV2h = fmaf(sst, y.w, aV2h);
    }

    // stage accumulated message + original node features into SMEM
    float* st = sStage[warp];
    st[lane]        = aS0;   st[32 + lane]  = aS1;
    st[64 + lane]   = aV0l;  st[96 + lane]  = aV0h;
    st[128 + lane]  = aV1l;  st[160 + lane] = aV1h;
    st[192 + lane]  = aV2l;  st[224 + lane] = aV2h;
    const float* nfp = nf + (size_t)n * 128;
    #pragma unroll
    for (int i = lane; i < 128; i += 32) st[256 + i] = nfp[i];
    __syncwarp();

    int spec = species[n];
    const float* Ws = W_sk_s + spec * 2048;   // (32,64)
    const float* Wv = W_sk_v + spec * 1024;   // (32,32)

    float gs0 = 0.f, gs1 = 0.f, gv0 = 0.f, gv1 = 0.f, gv2 = 0.f;
    #pragma unroll 8
    for (int m = 0; m < 64; m++) {
        float Sm = st[m];
        float V0 = st[64 + m], V1 = st[128 + m], V2 = st[192 + m];
        float a = sWs[m * 64 + lane];
        float b = sWs[m * 64 + 32 + lane];
        float c = sWv[m * 32 + lane];
        gs0 = fmaf(Sm, a, gs0); gs1 = fmaf(Sm, b, gs1);
        gv0 = fmaf(V0, c, gv0); gv1 = fmaf(V1, c, gv1); gv2 = fmaf(V2, c, gv2);
    }

    float sk0 = 0.f, sk1 = 0.f, sv0 = 0.f, sv1 = 0.f, sv2 = 0.f;
    #pragma unroll 8
    for (int m = 0; m < 32; m++) {
        float sm = st[256 + m];
        float v0 = st[288 + m * 3 + 0];
        float v1 = st[288 + m * 3 + 1];
        float v2 = st[288 + m * 3 + 2];
        float a = Ws[m * 64 + lane];
        float b = Ws[m * 64 + 32 + lane];
        float c = Wv[m * 32 + lane];
        sk0 = fmaf(sm, a, sk0); sk1 = fmaf(sm, b, sk1);
        sv0 = fmaf(v0, c, sv0); sv1 = fmaf(v1, c, sv1); sv2 = fmaf(v2, c, sv2);
    }

    const float A = 0.5f * 0.125f;                 // 0.5 * (2*MUL)^-0.5
    const float B = 0.5f * 0.17677669529663687f;   // 0.5 * MUL^-0.5
    float G0 = gs0 * A + sk0 * B;
    float G1 = gs1 * A + sk1 * B;
    float H0 = gv0 * A + sv0 * B;
    float H1 = gv1 * A + sv1 * B;
    float H2 = gv2 * A + sv2 * B;

    float feat = silu_f(G0);
    float gate = silu_f(G1);

    float* o = out + (size_t)n * 128;
    o[lane] = feat;
    o[32 + lane * 3 + 0] = H0 * gate;
    o[32 + lane * 3 + 1] = H1 * gate;
    o[32 + lane * 3 + 2] = H2 * gate;
}

// ---------------------------------------------------------------------------
extern "C" void kernel_launch(void* const* d_in, const int* in_sizes, int n_in,
                              void* d_out, int out_size) {
    const float* nf  = (const float*)d_in[0];
    const float* esh = (const float*)d_in[1];
    const float* rad = (const float*)d_in[2];
    const float* Wus = (const float*)d_in[3];
    const float* Wuv = (const float*)d_in[4];
    const float* Wr1 = (const float*)d_in[5];
    const float* Wr2 = (const float*)d_in[6];
    const float* Wds = (const float*)d_in[7];
    const float* Wdv = (const float*)d_in[8];
    const float* Wss = (const float*)d_in[9];
    const float* Wsv = (const float*)d_in[10];
    const int* snd  = (const int*)d_in[11];
    const int* rcv  = (const int*)d_in[12];
    const int* spec = (const int*)d_in[13];
    float* out = (float*)d_out;

    zero_cnt_kernel<<<32, 512>>>();
    hist_kernel<<<512, 512>>>(rcv);
    scan_kernel<<<1, 512>>>();
    scatter_kernel<<<512, 512>>>(rcv);
    up_kernel<<<2048, 128>>>(nf, Wus, Wuv);
    fused_node_kernel<<<2048, 256>>>(nf, esh, rad, Wr1, Wr2, Wds, Wdv,
                                     Wss, Wsv, snd, spec, out);
}

// round 3
// speedup vs baseline: 1.1149x; 1.1149x over previous
#include <cuda_runtime.h>

#define N_NODES 16384
#define N_EDGES 262144

// ---------------------------------------------------------------------------
// Static device scratch (no runtime allocation)
// ---------------------------------------------------------------------------
__device__ float  g_up[N_NODES * 128];    // [s1(32), v1x(32), v1y(32), v1z(32)]
__device__ float  g_acc[N_NODES * 256];   // [S(64), V0(64), V1(64), V2(64)]
__device__ int    g_cnt[N_NODES];
__device__ int    g_off[N_NODES + 1];
__device__ int    g_cursor[N_NODES];
__device__ int    g_ssnd[N_EDGES];        // receiver-sorted senders
__device__ int    g_srcv[N_EDGES];        // receiver-sorted receivers
__device__ float  g_srad[N_EDGES * 8];    // receiver-sorted radial
__device__ float4 g_ssh[N_EDGES];         // receiver-sorted edge_sh
__device__ float2 g_pUp[1024];            // packed (W_up_s, W_up_v)
__device__ float2 g_pDn2[2048];           // packed (W_dn_s[m][k], W_dn_s[m][32+k])
__device__ float  g_pDnV[2048];           // W_dn_v[m][k]
__device__ float4 g_pSk[4096];            // packed skip weights per species

__device__ __forceinline__ float silu_f(float x) {
    return x / (1.0f + __expf(-x));
}

// ---------------------------------------------------------------------------
// Prep: pack weight matrices + zero histogram. 92 blocks x 256 = 23552 threads
// ---------------------------------------------------------------------------
__global__ void prep_kernel(const float* __restrict__ Wus,
                            const float* __restrict__ Wuv,
                            const float* __restrict__ Wds,
                            const float* __restrict__ Wdv,
                            const float* __restrict__ Wss,
                            const float* __restrict__ Wsv) {
    int t = blockIdx.x * 256 + threadIdx.x;
    if (t < 1024) g_pUp[t] = make_float2(Wus[t], Wuv[t]);
    int i = t - 1024;
    if (i >= 0 && i < 2048) {
        int m = i >> 5, k = i & 31;
        g_pDn2[i] = make_float2(Wds[m * 64 + k], Wds[m * 64 + 32 + k]);
        g_pDnV[i] = Wdv[i];
    }
    int j = t - 3072;
    if (j >= 0 && j < 4096) {
        int sp = j >> 10, q = j & 1023, m = q >> 5, k = q & 31;
        g_pSk[j] = make_float4(Wss[sp * 2048 + m * 64 + k],
                               Wss[sp * 2048 + m * 64 + 32 + k],
                               Wsv[sp * 1024 + q], 0.f);
    }
    int z = t - 7168;
    if (z >= 0 && z < 16384) g_cnt[z] = 0;
}

// ---------------------------------------------------------------------------
// Zero accumulator (16 MB)
// ---------------------------------------------------------------------------
__global__ void zero_acc_kernel() {
    int i = blockIdx.x * blockDim.x + threadIdx.x;
    ((float4*)g_acc)[i] = make_float4(0.f, 0.f, 0.f, 0.f);
}

// ---------------------------------------------------------------------------
// CSR: histogram -> scan -> payload scatter (receiver-sorted edge arrays)
// ---------------------------------------------------------------------------
__global__ void hist_kernel(const int* __restrict__ receivers) {
    int e = blockIdx.x * blockDim.x + threadIdx.x;
    atomicAdd(&g_cnt[receivers[e]], 1);
}

__global__ void scan_kernel() {
    __shared__ int sPart[512];
    int t = threadIdx.x;
    int base = t * 32;
    int loc[32];
    int s = 0;
    #pragma unroll
    for (int j = 0; j < 32; j++) { loc[j] = s; s += g_cnt[base + j]; }
    sPart[t] = s;
    __syncthreads();
    #pragma unroll
    for (int off = 1; off < 512; off <<= 1) {
        int v = (t >= off) ? sPart[t - off] : 0;
        __syncthreads();
        sPart[t] += v;
        __syncthreads();
    }
    int prefix = (t == 0) ? 0 : sPart[t - 1];
    #pragma unroll
    for (int j = 0; j < 32; j++) {
        int o = prefix + loc[j];
        g_off[base + j] = o;
        g_cursor[base + j] = o;
    }
    if (t == 511) g_off[N_NODES] = prefix + s;
}

__global__ void scatter_kernel(const int* __restrict__ receivers,
                               const int* __restrict__ senders,
                               const float* __restrict__ esh,
                               const float* __restrict__ rad) {
    int e = blockIdx.x * blockDim.x + threadIdx.x;
    int r = receivers[e];
    int p = atomicAdd(&g_cursor[r], 1);
    g_ssnd[p] = senders[e];
    g_srcv[p] = r;
    g_ssh[p] = ((const float4*)esh)[e];
    float4 r0 = ((const float4*)rad)[e * 2];
    float4 r1 = ((const float4*)rad)[e * 2 + 1];
    ((float4*)g_srad)[p * 2]     = r0;
    ((float4*)g_srad)[p * 2 + 1] = r1;
}

// ---------------------------------------------------------------------------
// Up-projection: warp per node, packed weights, float4 broadcast staging
// ---------------------------------------------------------------------------
__global__ void __launch_bounds__(256) up_kernel(const float* __restrict__ nf) {
    __shared__ float2 sWu[1024];
    __shared__ float4 sF[8][32];
    int t = threadIdx.x;
    for (int i = t; i < 1024; i += 256) sWu[i] = g_pUp[i];
    __syncthreads();
    int warp = t >> 5, lane = t & 31;
    int n = blockIdx.x * 8 + warp;
    const float* f = nf + (size_t)n * 128;
    sF[warp][lane] = make_float4(f[lane], f[32 + 3 * lane],
                                 f[33 + 3 * lane], f[34 + 3 * lane]);
    __syncwarp();
    float os = 0.f, o0 = 0.f, o1 = 0.f, o2 = 0.f;
    #pragma unroll 8
    for (int m = 0; m < 32; m++) {
        float4 b = sF[warp][m];
        float2 w = sWu[m * 32 + lane];
        os = fmaf(b.x, w.x, os);
        o0 = fmaf(b.y, w.y, o0);
        o1 = fmaf(b.z, w.y, o1);
        o2 = fmaf(b.w, w.y, o2);
    }
    const float S = 0.17677669529663687f;
    float* u = g_up + (size_t)n * 128;
    u[lane]      = os * S;
    u[32 + lane] = o0 * S;
    u[64 + lane] = o1 * S;
    u[96 + lane] = o2 * S;
}

// ---------------------------------------------------------------------------
// Edge kernel: warp processes 8 receiver-sorted edges; register accumulation
// within equal-receiver runs, RED flush only at run boundaries.
// ---------------------------------------------------------------------------
__global__ void __launch_bounds__(256)
edge_kernel(const float* __restrict__ W_r1, const float* __restrict__ W_r2) {
    __shared__ float sW1[64];
    __shared__ float sW2[1024];
    __shared__ __align__(16) float smsg[8][256];
    int t = threadIdx.x;
    if (t < 64) sW1[t] = W_r1[t];
    for (int i = t; i < 1024; i += 256) sW2[i] = W_r2[i];
    __syncthreads();

    int warp = t >> 5, lane = t & 31, j8 = lane & 7;
    float* msg = smsg[warp];
    int p0 = (blockIdx.x * 8 + warp) * 8;

    const float INV_SQRT8 = 0.3535533905932738f;
    const float SC = INV_SQRT8 * 0.25f;          // radial scale * AVG_NEIGH^-0.5
    const float INV_SQRT3 = 0.5773502691896258f;

    float aS0 = 0.f, aS1 = 0.f;
    float aV0l = 0.f, aV0h = 0.f, aV1l = 0.f, aV1h = 0.f, aV2l = 0.f, aV2h = 0.f;
    int cur = g_srcv[p0];

    for (int i = 0; i < 8; i++) {
        int p = p0 + i;
        int r = g_srcv[p];
        if (r != cur) {
            msg[lane]       = aS0;  msg[32 + lane]  = aS1;
            msg[64 + lane]  = aV0l; msg[96 + lane]  = aV0h;
            msg[128 + lane] = aV1l; msg[160 + lane] = aV1h;
            msg[192 + lane] = aV2l; msg[224 + lane] = aV2h;
            __syncwarp();
            float* dst = g_acc + (size_t)cur * 256;
            #pragma unroll
            for (int q = 0; q < 2; q++) {
                float4 v = ((const float4*)msg)[q * 32 + lane];
                asm volatile("red.global.add.v4.f32 [%0], {%1,%2,%3,%4};"
                             :: "l"(dst + (q * 32 + lane) * 4),
                                "f"(v.x), "f"(v.y), "f"(v.z), "f"(v.w)
                             : "memory");
            }
            __syncwarp();
            aS0 = aS1 = aV0l = aV0h = aV1l = aV1h = aV2l = aV2h = 0.f;
            cur = r;
        }

        int snd = g_ssnd[p];
        float rv = (lane < 8) ? g_srad[p * 8 + lane] : 0.f;
        float pre = 0.f;
        #pragma unroll
        for (int k = 0; k < 8; k++) {
            float rk = __shfl_sync(0xffffffffu, rv, k);
            pre = fmaf(rk, sW1[k * 8 + j8], pre);
        }
        float h = silu_f(pre * INV_SQRT8);

        float w0 = 0.f, w1 = 0.f, w2 = 0.f, w3 = 0.f;
        #pragma unroll
        for (int j = 0; j < 8; j++) {
            float hj = __shfl_sync(0xffffffffu, h, j);
            w0 = fmaf(hj, sW2[j * 128 + lane], w0);
            w1 = fmaf(hj, sW2[j * 128 + 32 + lane], w1);
            w2 = fmaf(hj, sW2[j * 128 + 64 + lane], w2);
            w3 = fmaf(hj, sW2[j * 128 + 96 + lane], w3);
        }
        w0 *= SC; w1 *= SC; w2 *= SC; w3 *= SC;

        const float* up = g_up + (size_t)snd * 128;
        float ss  = up[lane];
        float vs0 = up[32 + lane];
        float vs1 = up[64 + lane];
        float vs2 = up[96 + lane];
        float4 y = g_ssh[p];

        float dot = (vs0 * y.y + vs1 * y.z + vs2 * y.w) * INV_SQRT3;
        float sst = ss * w2;

        aS0  = fmaf(ss,  w0, aS0);
        aS1  = fmaf(dot, w3, aS1);
        aV0l = fmaf(vs0, w1, aV0l);  aV0h = fmaf(sst, y.y, aV0h);
        aV1l = fmaf(vs1, w1, aV1l);  aV1h = fmaf(sst, y.z, aV1h);
        aV2l = fmaf(vs2, w1, aV2l);  aV2h = fmaf(sst, y.w, aV2h);
    }

    // final flush
    msg[lane]       = aS0;  msg[32 + lane]  = aS1;
    msg[64 + lane]  = aV0l; msg[96 + lane]  = aV0h;
    msg[128 + lane] = aV1l; msg[160 + lane] = aV1h;
    msg[192 + lane] = aV2l; msg[224 + lane] = aV2h;
    __syncwarp();
    float* dst = g_acc + (size_t)cur * 256;
    #pragma unroll
    for (int q = 0; q < 2; q++) {
        float4 v = ((const float4*)msg)[q * 32 + lane];
        asm volatile("red.global.add.v4.f32 [%0], {%1,%2,%3,%4};"
                     :: "l"(dst + (q * 32 + lane) * 4),
                        "f"(v.x), "f"(v.y), "f"(v.z), "f"(v.w)
                     : "memory");
    }
}

// ---------------------------------------------------------------------------
// Down-projection + skip + gating: 2 nodes per warp, packed weights,
// float4 broadcast staging. Block = 128 threads (4 warps, 8 nodes).
// ---------------------------------------------------------------------------
__global__ void __launch_bounds__(128)
down_kernel(const float* __restrict__ nf,
            const int* __restrict__ species,
            float* __restrict__ out) {
    __shared__ float2 sW2d[2048];
    __shared__ float  sWvd[2048];
    __shared__ float4 sSt[4][2][96];   // [warp][node][ 0:64 acc | 64:96 nf ]
    int t = threadIdx.x;
    for (int i = t; i < 2048; i += 128) { sW2d[i] = g_pDn2[i]; sWvd[i] = g_pDnV[i]; }
    __syncthreads();

    int warp = t >> 5, lane = t & 31;
    int n0 = blockIdx.x * 8 + warp * 2;

    #pragma unroll
    for (int u = 0; u < 2; u++) {
        int n = n0 + u;
        const float* acc = g_acc + (size_t)n * 256;
        sSt[warp][u][lane] = make_float4(acc[lane], acc[64 + lane],
                                         acc[128 + lane], acc[192 + lane]);
        sSt[warp][u][32 + lane] = make_float4(acc[32 + lane], acc[96 + lane],
                                              acc[160 + lane], acc[224 + lane]);
        const float* f = nf + (size_t)n * 128;
        sSt[warp][u][64 + lane] = make_float4(f[lane], f[32 + 3 * lane],
                                              f[33 + 3 * lane], f[34 + 3 * lane]);
    }
    __syncwarp();

    const float4* st0 = sSt[warp][0];
    const float4* st1 = sSt[warp][1];

    float g00 = 0.f, g01 = 0.f, g02 = 0.f, g03 = 0.f, g04 = 0.f;
    float g10 = 0.f, g11 = 0.f, g12 = 0.f, g13 = 0.f, g14 = 0.f;
    #pragma unroll 4
    for (int m = 0; m < 64; m++) {
        float2 w  = sW2d[m * 32 + lane];
        float  wv = sWvd[m * 32 + lane];
        float4 b0 = st0[m];
        float4 b1 = st1[m];
        g00 = fmaf(b0.x, w.x, g00); g01 = fmaf(b0.x, w.y, g01);
        g02 = fmaf(b0.y, wv, g02);  g03 = fmaf(b0.z, wv, g03); g04 = fmaf(b0.w, wv, g04);
        g10 = fmaf(b1.x, w.x, g10); g11 = fmaf(b1.x, w.y, g11);
        g12 = fmaf(b1.y, wv, g12);  g13 = fmaf(b1.z, wv, g13); g14 = fmaf(b1.w, wv, g14);
    }

    int sp0 = species[n0];
    int sp1 = species[n0 + 1];
    const float4* Wk0 = g_pSk + sp0 * 1024;
    const float4* Wk1 = g_pSk + sp1 * 1024;

    float s00 = 0.f, s01 = 0.f, s02 = 0.f, s03 = 0.f, s04 = 0.f;
    float s10 = 0.f, s11 = 0.f, s12 = 0.f, s13 = 0.f, s14 = 0.f;
    #pragma unroll 4
    for (int m = 0; m < 32; m++) {
        float4 w0 = __ldg(&Wk0[m * 32 + lane]);
        float4 w1 = __ldg(&Wk1[m * 32 + lane]);
        float4 c0 = st0[64 + m];
        float4 c1 = st1[64 + m];
        s00 = fmaf(c0.x, w0.x, s00); s01 = fmaf(c0.x, w0.y, s01);
        s02 = fmaf(c0.y, w0.z, s02); s03 = fmaf(c0.z, w0.z, s03); s04 = fmaf(c0.w, w0.z, s04);
        s10 = fmaf(c1.x, w1.x, s10); s11 = fmaf(c1.x, w1.y, s11);
        s12 = fmaf(c1.y, w1.z, s12); s13 = fmaf(c1.z, w1.z, s13); s14 = fmaf(c1.w, w1.z, s14);
    }

    const float A = 0.5f * 0.125f;                 // 0.5 * (2*MUL)^-0.5
    const float B = 0.5f * 0.17677669529663687f;   // 0.5 * MUL^-0.5

    {
        float G0 = g00 * A + s00 * B;
        float G1 = g01 * A + s01 * B;
        float H0 = g02 * A + s02 * B;
        float H1 = g03 * A + s03 * B;
        float H2 = g04 * A + s04 * B;
        float feat = silu_f(G0);
        float gate = silu_f(G1);
        float* o = out + (size_t)n0 * 128;
        o[lane] = feat;
        o[32 + lane * 3 + 0] = H0 * gate;
        o[32 + lane * 3 + 1] = H1 * gate;
        o[32 + lane * 3 + 2] = H2 * gate;
    }
    {
        float G0 = g10 * A + s10 * B;
        float G1 = g11 * A + s11 * B;
        float H0 = g12 * A + s12 * B;
        float H1 = g13 * A + s13 * B;
        float H2 = g14 * A + s14 * B;
        float feat = silu_f(G0);
        float gate = silu_f(G1);
        float* o = out + (size_t)(n0 + 1) * 128;
        o[lane] = feat;
        o[32 + lane * 3 + 0] = H0 * gate;
        o[32 + lane * 3 + 1] = H1 * gate;
        o[32 + lane * 3 + 2] = H2 * gate;
    }
}

// ---------------------------------------------------------------------------
extern "C" void kernel_launch(void* const* d_in, const int* in_sizes, int n_in,
                              void* d_out, int out_size) {
    const float* nf  = (const float*)d_in[0];
    const float* esh = (const float*)d_in[1];
    const float* rad = (const float*)d_in[2];
    const float* Wus = (const float*)d_in[3];
    const float* Wuv = (const float*)d_in[4];
    const float* Wr1 = (const float*)d_in[5];
    const float* Wr2 = (const float*)d_in[6];
    const float* Wds = (const float*)d_in[7];
    const float* Wdv = (const float*)d_in[8];
    const float* Wss = (const float*)d_in[9];
    const float* Wsv = (const float*)d_in[10];
    const int* snd  = (const int*)d_in[11];
    const int* rcv  = (const int*)d_in[12];
    const int* spec = (const int*)d_in[13];
    float* out = (float*)d_out;

    prep_kernel<<<92, 256>>>(Wus, Wuv, Wds, Wdv, Wss, Wsv);
    zero_acc_kernel<<<4096, 256>>>();
    hist_kernel<<<512, 512>>>(rcv);
    scan_kernel<<<1, 512>>>();
    scatter_kernel<<<512, 512>>>(rcv, snd, esh, rad);
    up_kernel<<<2048, 256>>>(nf);
    edge_kernel<<<4096, 256>>>(Wr1, Wr2);
    down_kernel<<<2048, 128>>>(nf, spec, out);
}

// round 4
// speedup vs baseline: 1.3798x; 1.2375x over previous
#include <cuda_runtime.h>

#define N_NODES 16384
#define N_EDGES 262144

// ---------------------------------------------------------------------------
// Static device scratch (no runtime allocation)
// ---------------------------------------------------------------------------
__device__ float  g_up[N_NODES * 128];    // lane-interleaved: [n][lane][4] = (s1, v1x, v1y, v1z)
__device__ float  g_acc[N_NODES * 256];   // [S(64), V0(64), V1(64), V2(64)]
__device__ int    g_cnt[N_NODES];
__device__ int    g_cursor[N_NODES];
__device__ int    g_base;
__device__ int    g_ssnd[N_EDGES];        // receiver-sorted senders
__device__ int    g_srcv[N_EDGES];        // receiver-sorted receivers
__device__ float  g_srad[N_EDGES * 8];    // receiver-sorted radial
__device__ float4 g_ssh[N_EDGES];         // receiver-sorted edge_sh
__device__ float2 g_pUp[1024];            // packed (W_up_s, W_up_v)
__device__ float2 g_pDn2[2048];           // packed (W_dn_s[m][k], W_dn_s[m][32+k])
__device__ float  g_pDnV[2048];           // W_dn_v[m][k]
__device__ float4 g_pSk[4096];            // packed skip weights per species

__device__ __forceinline__ float silu_f(float x) {
    return x / (1.0f + __expf(-x));
}

// ---------------------------------------------------------------------------
// K1 prep: pack weights + zero histogram + zero base. 92 x 256
// ---------------------------------------------------------------------------
__global__ void prep_kernel(const float* __restrict__ Wus,
                            const float* __restrict__ Wuv,
                            const float* __restrict__ Wds,
                            const float* __restrict__ Wdv,
                            const float* __restrict__ Wss,
                            const float* __restrict__ Wsv) {
    int t = blockIdx.x * 256 + threadIdx.x;
    if (t == 0) g_base = 0;
    if (t < 1024) g_pUp[t] = make_float2(Wus[t], Wuv[t]);
    int i = t - 1024;
    if (i >= 0 && i < 2048) {
        int m = i >> 5, k = i & 31;
        g_pDn2[i] = make_float2(Wds[m * 64 + k], Wds[m * 64 + 32 + k]);
        g_pDnV[i] = Wdv[i];
    }
    int j = t - 3072;
    if (j >= 0 && j < 4096) {
        int sp = j >> 10, q = j & 1023, m = q >> 5, k = q & 31;
        g_pSk[j] = make_float4(Wss[sp * 2048 + m * 64 + k],
                               Wss[sp * 2048 + m * 64 + 32 + k],
                               Wsv[sp * 1024 + q], 0.f);
    }
    int z = t - 7168;
    if (z >= 0 && z < 16384) g_cnt[z] = 0;
}

// ---------------------------------------------------------------------------
// K2 fused setup: zero_acc (blocks 0..4095) + hist (4096..5119) + up (5120..7167)
// ---------------------------------------------------------------------------
__global__ void __launch_bounds__(256)
setup_kernel(const float* __restrict__ nf, const int* __restrict__ rcv) {
    int b = blockIdx.x;
    int t = threadIdx.x;
    if (b < 4096) {                                   // zero accumulator (16 MB)
        ((float4*)g_acc)[b * 256 + t] = make_float4(0.f, 0.f, 0.f, 0.f);
        return;
    }
    if (b < 5120) {                                   // receiver histogram
        int e = (b - 4096) * 256 + t;
        atomicAdd(&g_cnt[rcv[e]], 1);
        return;
    }
    // up-projection: 8 nodes per block (warp per node), packed weights
    __shared__ float2 sWu[1024];
    __shared__ float4 sF[8][32];
    for (int i = t; i < 1024; i += 256) sWu[i] = g_pUp[i];
    __syncthreads();
    int warp = t >> 5, lane = t & 31;
    int n = (b - 5120) * 8 + warp;
    const float* f = nf + (size_t)n * 128;
    sF[warp][lane] = make_float4(f[lane], f[32 + 3 * lane],
                                 f[33 + 3 * lane], f[34 + 3 * lane]);
    __syncwarp();
    float os = 0.f, o0 = 0.f, o1 = 0.f, o2 = 0.f;
    #pragma unroll 8
    for (int m = 0; m < 32; m++) {
        float4 v = sF[warp][m];
        float2 w = sWu[m * 32 + lane];
        os = fmaf(v.x, w.x, os);
        o0 = fmaf(v.y, w.y, o0);
        o1 = fmaf(v.z, w.y, o1);
        o2 = fmaf(v.w, w.y, o2);
    }
    const float S = 0.17677669529663687f;
    ((float4*)g_up)[n * 32 + lane] = make_float4(os * S, o0 * S, o1 * S, o2 * S);
}

// ---------------------------------------------------------------------------
// K3 parallel scan: block-local scan + atomic global base (block order is
// irrelevant — CSR runs only need contiguity). 64 blocks x 256.
// ---------------------------------------------------------------------------
__global__ void __launch_bounds__(256) scan_kernel() {
    __shared__ int sWarp[8];
    __shared__ int sBase;
    int t = threadIdx.x;
    int lane = t & 31, warp = t >> 5;
    int n = blockIdx.x * 256 + t;
    int c = g_cnt[n];
    int incl = c;
    #pragma unroll
    for (int o = 1; o < 32; o <<= 1) {
        int v = __shfl_up_sync(0xffffffffu, incl, o);
        if (lane >= o) incl += v;
    }
    if (lane == 31) sWarp[warp] = incl;
    __syncthreads();
    if (t < 8) {
        int v = sWarp[t];
        #pragma unroll
        for (int o = 1; o < 8; o <<= 1) {
            int u = __shfl_up_sync(0xffu, v, o);
            if (t >= o) v += u;
        }
        sWarp[t] = v;
        if (t == 7) sBase = atomicAdd(&g_base, v);
    }
    __syncthreads();
    int warpBase = (warp > 0) ? sWarp[warp - 1] : 0;
    g_cursor[n] = sBase + warpBase + incl - c;
}

// ---------------------------------------------------------------------------
// K4 scatter: physically reorder edge payloads into receiver-sorted order
// ---------------------------------------------------------------------------
__global__ void scatter_kernel(const int* __restrict__ receivers,
                               const int* __restrict__ senders,
                               const float* __restrict__ esh,
                               const float* __restrict__ rad) {
    int e = blockIdx.x * blockDim.x + threadIdx.x;
    int r = receivers[e];
    int p = atomicAdd(&g_cursor[r], 1);
    g_ssnd[p] = senders[e];
    g_srcv[p] = r;
    g_ssh[p] = ((const float4*)esh)[e];
    ((float4*)g_srad)[p * 2]     = ((const float4*)rad)[e * 2];
    ((float4*)g_srad)[p * 2 + 1] = ((const float4*)rad)[e * 2 + 1];
}

// ---------------------------------------------------------------------------
// K5 edge kernel: warp handles 8 receiver-sorted edges. Batched header loads,
// single LDG.128 sender gather, register run accumulation, RED at boundaries.
// ---------------------------------------------------------------------------
__global__ void __launch_bounds__(256)
edge_kernel(const float* __restrict__ W_r1, const float* __restrict__ W_r2) {
    __shared__ float sW1[64];
    __shared__ float sW2[1024];
    __shared__ __align__(16) float smsg[8][256];
    int t = threadIdx.x;
    if (t < 64) sW1[t] = W_r1[t];
    for (int i = t; i < 1024; i += 256) sW2[i] = W_r2[i];
    __syncthreads();

    int warp = t >> 5, lane = t & 31, j8 = lane & 7;
    float* msg = smsg[warp];
    int p0 = (blockIdx.x * 8 + warp) * 8;

    const float INV_SQRT8 = 0.3535533905932738f;
    const float SC = INV_SQRT8 * 0.25f;          // radial scale * AVG_NEIGH^-0.5
    const float INV_SQRT3 = 0.5773502691896258f;

    // batched coalesced header loads for 8 edges
    int   sndv = (lane < 8) ? g_ssnd[p0 + lane] : 0;
    int   rcvv = (lane < 8) ? g_srcv[p0 + lane] : 0;
    float shv  = ((const float*)g_ssh)[p0 * 4 + lane];   // 8 x float4
    float rA   = g_srad[p0 * 8 + lane];                  // radial edges 0-3
    float rB   = g_srad[p0 * 8 + 32 + lane];             // radial edges 4-7

    float aS0 = 0.f, aS1 = 0.f;
    float aV0l = 0.f, aV0h = 0.f, aV1l = 0.f, aV1h = 0.f, aV2l = 0.f, aV2h = 0.f;
    int cur = __shfl_sync(0xffffffffu, rcvv, 0);

    #pragma unroll
    for (int i = 0; i < 8; i++) {
        int r = __shfl_sync(0xffffffffu, rcvv, i);
        if (r != cur) {
            msg[lane]       = aS0;  msg[32 + lane]  = aS1;
            msg[64 + lane]  = aV0l; msg[96 + lane]  = aV0h;
            msg[128 + lane] = aV1l; msg[160 + lane] = aV1h;
            msg[192 + lane] = aV2l; msg[224 + lane] = aV2h;
            __syncwarp();
            float* dst = g_acc + (size_t)cur * 256;
            #pragma unroll
            for (int q = 0; q < 2; q++) {
                float4 v = ((const float4*)msg)[q * 32 + lane];
                asm volatile("red.global.add.v4.f32 [%0], {%1,%2,%3,%4};"
                             :: "l"(dst + (q * 32 + lane) * 4),
                                "f"(v.x), "f"(v.y), "f"(v.z), "f"(v.w)
                             : "memory");
            }
            __syncwarp();
            aS0 = aS1 = aV0l = aV0h = aV1l = aV1h = aV2l = aV2h = 0.f;
            cur = r;
        }

        int snd = __shfl_sync(0xffffffffu, sndv, i);
        float y0 = __shfl_sync(0xffffffffu, shv, i * 4 + 1);
        float y1 = __shfl_sync(0xffffffffu, shv, i * 4 + 2);
        float y2 = __shfl_sync(0xffffffffu, shv, i * 4 + 3);
        float rsrc = (i < 4) ? rA : rB;
        int rbase = (i & 3) * 8;

        float pre = 0.f;
        #pragma unroll
        for (int k = 0; k < 8; k++) {
            float rk = __shfl_sync(0xffffffffu, rsrc, rbase + k);
            pre = fmaf(rk, sW1[k * 8 + j8], pre);
        }
        float h = silu_f(pre * INV_SQRT8);

        float w0 = 0.f, w1 = 0.f, w2 = 0.f, w3 = 0.f;
        #pragma unroll
        for (int j = 0; j < 8; j++) {
            float hj = __shfl_sync(0xffffffffu, h, j);
            w0 = fmaf(hj, sW2[j * 128 + lane], w0);
            w1 = fmaf(hj, sW2[j * 128 + 32 + lane], w1);
            w2 = fmaf(hj, sW2[j * 128 + 64 + lane], w2);
            w3 = fmaf(hj, sW2[j * 128 + 96 + lane], w3);
        }
        w0 *= SC; w1 *= SC; w2 *= SC; w3 *= SC;

        // single vectorized gather of sender up-features (lane-interleaved)
        float4 u = ((const float4*)g_up)[snd * 32 + lane];

        float dot = (u.y * y0 + u.z * y1 + u.w * y2) * INV_SQRT3;
        float sst = u.x * w2;

        aS0  = fmaf(u.x, w0, aS0);
        aS1  = fmaf(dot, w3, aS1);
        aV0l = fmaf(u.y, w1, aV0l);  aV0h = fmaf(sst, y0, aV0h);
        aV1l = fmaf(u.z, w1, aV1l);  aV1h = fmaf(sst, y1, aV1h);
        aV2l = fmaf(u.w, w1, aV2l);  aV2h = fmaf(sst, y2, aV2h);
    }

    // final flush
    msg[lane]       = aS0;  msg[32 + lane]  = aS1;
    msg[64 + lane]  = aV0l; msg[96 + lane]  = aV0h;
    msg[128 + lane] = aV1l; msg[160 + lane] = aV1h;
    msg[192 + lane] = aV2l; msg[224 + lane] = aV2h;
    __syncwarp();
    float* dst = g_acc + (size_t)cur * 256;
    #pragma unroll
    for (int q = 0; q < 2; q++) {
        float4 v = ((const float4*)msg)[q * 32 + lane];
        asm volatile("red.global.add.v4.f32 [%0], {%1,%2,%3,%4};"
                     :: "l"(dst + (q * 32 + lane) * 4),
                        "f"(v.x), "f"(v.y), "f"(v.z), "f"(v.w)
                     : "memory");
    }
}

// ---------------------------------------------------------------------------
// K6 down-projection + skip + gating: 2 nodes per warp, packed weights
// ---------------------------------------------------------------------------
__global__ void __launch_bounds__(128)
down_kernel(const float* __restrict__ nf,
            const int* __restrict__ species,
            float* __restrict__ out) {
    __shared__ float2 sW2d[2048];
    __shared__ float  sWvd[2048];
    __shared__ float4 sSt[4][2][96];   // [warp][node][ 0:64 acc | 64:96 nf ]
    int t = threadIdx.x;
    for (int i = t; i < 2048; i += 128) { sW2d[i] = g_pDn2[i]; sWvd[i] = g_pDnV[i]; }
    __syncthreads();

    int warp = t >> 5, lane = t & 31;
    int n0 = blockIdx.x * 8 + warp * 2;

    #pragma unroll
    for (int u = 0; u < 2; u++) {
        int n = n0 + u;
        const float* acc = g_acc + (size_t)n * 256;
        sSt[warp][u][lane] = make_float4(acc[lane], acc[64 + lane],
                                         acc[128 + lane], acc[192 + lane]);
        sSt[warp][u][32 + lane] = make_float4(acc[32 + lane], acc[96 + lane],
                                              acc[160 + lane], acc[224 + lane]);
        const float* f = nf + (size_t)n * 128;
        sSt[warp][u][64 + lane] = make_float4(f[lane], f[32 + 3 * lane],
                                              f[33 + 3 * lane], f[34 + 3 * lane]);
    }
    __syncwarp();

    const float4* st0 = sSt[warp][0];
    const float4* st1 = sSt[warp][1];

    float g00 = 0.f, g01 = 0.f, g02 = 0.f, g03 = 0.f, g04 = 0.f;
    float g10 = 0.f, g11 = 0.f, g12 = 0.f, g13 = 0.f, g14 = 0.f;
    #pragma unroll 4
    for (int m = 0; m < 64; m++) {
        float2 w  = sW2d[m * 32 + lane];
        float  wv = sWvd[m * 32 + lane];
        float4 b0 = st0[m];
        float4 b1 = st1[m];
        g00 = fmaf(b0.x, w.x, g00); g01 = fmaf(b0.x, w.y, g01);
        g02 = fmaf(b0.y, wv, g02);  g03 = fmaf(b0.z, wv, g03); g04 = fmaf(b0.w, wv, g04);
        g10 = fmaf(b1.x, w.x, g10); g11 = fmaf(b1.x, w.y, g11);
        g12 = fmaf(b1.y, wv, g12);  g13 = fmaf(b1.z, wv, g13); g14 = fmaf(b1.w, wv, g14);
    }

    int sp0 = species[n0];
    int sp1 = species[n0 + 1];
    const float4* Wk0 = g_pSk + sp0 * 1024;
    const float4* Wk1 = g_pSk + sp1 * 1024;

    float s00 = 0.f, s01 = 0.f, s02 = 0.f, s03 = 0.f, s04 = 0.f;
    float s10 = 0.f, s11 = 0.f, s12 = 0.f, s13 = 0.f, s14 = 0.f;
    #pragma unroll 4
    for (int m = 0; m < 32; m++) {
        float4 w0 = __ldg(&Wk0[m * 32 + lane]);
        float4 w1 = __ldg(&Wk1[m * 32 + lane]);
        float4 c0 = st0[64 + m];
        float4 c1 = st1[64 + m];
        s00 = fmaf(c0.x, w0.x, s00); s01 = fmaf(c0.x, w0.y, s01);
        s02 = fmaf(c0.y, w0.z, s02); s03 = fmaf(c0.z, w0.z, s03); s04 = fmaf(c0.w, w0.z, s04);
        s10 = fmaf(c1.x, w1.x, s10); s11 = fmaf(c1.x, w1.y, s11);
        s12 = fmaf(c1.y, w1.z, s12); s13 = fmaf(c1.z, w1.z, s13); s14 = fmaf(c1.w, w1.z, s14);
    }

    const float A = 0.5f * 0.125f;                 // 0.5 * (2*MUL)^-0.5
    const float B = 0.5f * 0.17677669529663687f;   // 0.5 * MUL^-0.5

    {
        float G0 = g00 * A + s00 * B;
        float G1 = g01 * A + s01 * B;
        float H0 = g02 * A + s02 * B;
        float H1 = g03 * A + s03 * B;
        float H2 = g04 * A + s04 * B;
        float feat = silu_f(G0);
        float gate = silu_f(G1);
        float* o = out + (size_t)n0 * 128;
        o[lane] = feat;
        o[32 + lane * 3 + 0] = H0 * gate;
        o[32 + lane * 3 + 1] = H1 * gate;
        o[32 + lane * 3 + 2] = H2 * gate;
    }
    {
        float G0 = g10 * A + s10 * B;
        float G1 = g11 * A + s11 * B;
        float H0 = g12 * A + s12 * B;
        float H1 = g13 * A + s13 * B;
        float H2 = g14 * A + s14 * B;
        float feat = silu_f(G0);
        float gate = silu_f(G1);
        float* o = out + (size_t)(n0 + 1) * 128;
        o[lane] = feat;
        o[32 + lane * 3 + 0] = H0 * gate;
        o[32 + lane * 3 + 1] = H1 * gate;
        o[32 + lane * 3 + 2] = H2 * gate;
    }
}

// ---------------------------------------------------------------------------
extern "C" void kernel_launch(void* const* d_in, const int* in_sizes, int n_in,
                              void* d_out, int out_size) {
    const float* nf  = (const float*)d_in[0];
    const float* esh = (const float*)d_in[1];
    const float* rad = (const float*)d_in[2];
    const float* Wus = (const float*)d_in[3];
    const float* Wuv = (const float*)d_in[4];
    const float* Wr1 = (const float*)d_in[5];
    const float* Wr2 = (const float*)d_in[6];
    const float* Wds = (const float*)d_in[7];
    const float* Wdv = (const float*)d_in[8];
    const float* Wss = (const float*)d_in[9];
    const float* Wsv = (const float*)d_in[10];
    const int* snd  = (const int*)d_in[11];
    const int* rcv  = (const int*)d_in[12];
    const int* spec = (const int*)d_in[13];
    float* out = (float*)d_out;

    prep_kernel<<<92, 256>>>(Wus, Wuv, Wds, Wdv, Wss, Wsv);
    setup_kernel<<<7168, 256>>>(nf, rcv);
    scan_kernel<<<64, 256>>>();
    scatter_kernel<<<512, 512>>>(rcv, snd, esh, rad);
    edge_kernel<<<4096, 256>>>(Wr1, Wr2);
    down_kernel<<<2048, 128>>>(nf, spec, out);
}

// round 5
// speedup vs baseline: 1.8665x; 1.3528x over previous
#include <cuda_runtime.h>

#define N_NODES 16384
#define N_EDGES 262144

typedef unsigned long long ull;

// ---------------------------------------------------------------------------
// Static device scratch (no runtime allocation)
// ---------------------------------------------------------------------------
__device__ float  g_up[N_NODES * 128];     // [n][lane][4] = (s1, v1x, v1y, v1z)
__device__ float  g_acc[N_NODES * 256];    // [n][lane][8] = (S0,S1,V0l,V0h,V1l,V1h,V2l,V2h)
__device__ int    g_cnt[N_NODES];
__device__ int    g_cursor[N_NODES];
__device__ int    g_base;
__device__ float4 g_sedge[N_EDGES * 4];    // 64B/edge: q0(snd,rcv,y1,y2) q1(y3,r0,r1,r2) q2(r3..r6) q3(r7,0,0,0)
__device__ float2 g_pUp[1024];             // packed (W_up_s, W_up_v)
__device__ float2 g_pDn2[2048];            // packed (W_dn_s[m][k], W_dn_s[m][32+k])
__device__ float  g_pDnV[2048];            // W_dn_v[m][k]
__device__ float4 g_pSk[4096];             // packed skip weights per species

__device__ __forceinline__ float silu_f(float x) {
    return x / (1.0f + __expf(-x));
}

__device__ __forceinline__ ull pk2(float a, float b) {
    ull r; asm("mov.b64 %0, {%1,%2};" : "=l"(r) : "f"(a), "f"(b)); return r;
}
__device__ __forceinline__ void upk2(float& a, float& b, ull v) {
    asm("mov.b64 {%0,%1}, %2;" : "=f"(a), "=f"(b) : "l"(v));
}
__device__ __forceinline__ ull fma2_(ull a, ull b, ull c) {
    ull d; asm("fma.rn.f32x2 %0, %1, %2, %3;" : "=l"(d) : "l"(a), "l"(b), "l"(c)); return d;
}

// ---------------------------------------------------------------------------
// K1 prep: pack weights + zero histogram + zero base. 92 x 256
// ---------------------------------------------------------------------------
__global__ void prep_kernel(const float* __restrict__ Wus,
                            const float* __restrict__ Wuv,
                            const float* __restrict__ Wds,
                            const float* __restrict__ Wdv,
                            const float* __restrict__ Wss,
                            const float* __restrict__ Wsv) {
    int t = blockIdx.x * 256 + threadIdx.x;
    if (t == 0) g_base = 0;
    if (t < 1024) g_pUp[t] = make_float2(Wus[t], Wuv[t]);
    int i = t - 1024;
    if (i >= 0 && i < 2048) {
        int m = i >> 5, k = i & 31;
        g_pDn2[i] = make_float2(Wds[m * 64 + k], Wds[m * 64 + 32 + k]);
        g_pDnV[i] = Wdv[i];
    }
    int j = t - 3072;
    if (j >= 0 && j < 4096) {
        int sp = j >> 10, q = j & 1023, m = q >> 5, k = q & 31;
        g_pSk[j] = make_float4(Wss[sp * 2048 + m * 64 + k],
                               Wss[sp * 2048 + m * 64 + 32 + k],
                               Wsv[sp * 1024 + q], 0.f);
    }
    int z = t - 7168;
    if (z >= 0 && z < 16384) g_cnt[z] = 0;
}

// ---------------------------------------------------------------------------
// K2 fused setup: zero_acc (0..4095) + hist (4096..5119) + up (5120..7167)
// ---------------------------------------------------------------------------
__global__ void __launch_bounds__(256)
setup_kernel(const float* __restrict__ nf, const int* __restrict__ rcv) {
    int b = blockIdx.x;
    int t = threadIdx.x;
    if (b < 4096) {
        ((float4*)g_acc)[b * 256 + t] = make_float4(0.f, 0.f, 0.f, 0.f);
        return;
    }
    if (b < 5120) {
        int e = (b - 4096) * 256 + t;
        atomicAdd(&g_cnt[rcv[e]], 1);
        return;
    }
    __shared__ float2 sWu[1024];
    __shared__ float4 sF[8][32];
    for (int i = t; i < 1024; i += 256) sWu[i] = g_pUp[i];
    __syncthreads();
    int warp = t >> 5, lane = t & 31;
    int n = (b - 5120) * 8 + warp;
    const float* f = nf + (size_t)n * 128;
    sF[warp][lane] = make_float4(f[lane], f[32 + 3 * lane],
                                 f[33 + 3 * lane], f[34 + 3 * lane]);
    __syncwarp();
    float os = 0.f, o0 = 0.f, o1 = 0.f, o2 = 0.f;
    #pragma unroll 8
    for (int m = 0; m < 32; m++) {
        float4 v = sF[warp][m];
        float2 w = sWu[m * 32 + lane];
        os = fmaf(v.x, w.x, os);
        o0 = fmaf(v.y, w.y, o0);
        o1 = fmaf(v.z, w.y, o1);
        o2 = fmaf(v.w, w.y, o2);
    }
    const float S = 0.17677669529663687f;
    ((float4*)g_up)[n * 32 + lane] = make_float4(os * S, o0 * S, o1 * S, o2 * S);
}

// ---------------------------------------------------------------------------
// K3 parallel scan: block-local scan + atomic global base
// ---------------------------------------------------------------------------
__global__ void __launch_bounds__(256) scan_kernel() {
    __shared__ int sWarp[8];
    __shared__ int sBase;
    int t = threadIdx.x;
    int lane = t & 31, warp = t >> 5;
    int n = blockIdx.x * 256 + t;
    int c = g_cnt[n];
    int incl = c;
    #pragma unroll
    for (int o = 1; o < 32; o <<= 1) {
        int v = __shfl_up_sync(0xffffffffu, incl, o);
        if (lane >= o) incl += v;
    }
    if (lane == 31) sWarp[warp] = incl;
    __syncthreads();
    if (t < 8) {
        int v = sWarp[t];
        #pragma unroll
        for (int o = 1; o < 8; o <<= 1) {
            int u = __shfl_up_sync(0xffu, v, o);
            if (t >= o) v += u;
        }
        sWarp[t] = v;
        if (t == 7) sBase = atomicAdd(&g_base, v);
    }
    __syncthreads();
    int warpBase = (warp > 0) ? sWarp[warp - 1] : 0;
    g_cursor[n] = sBase + warpBase + incl - c;
}

// ---------------------------------------------------------------------------
// K4 scatter: reorder edge payloads into 64B structs, receiver-sorted
// ---------------------------------------------------------------------------
__global__ void scatter_kernel(const int* __restrict__ receivers,
                               const int* __restrict__ senders,
                               const float* __restrict__ esh,
                               const float* __restrict__ rad) {
    int e = blockIdx.x * blockDim.x + threadIdx.x;
    int r = receivers[e];
    int s = senders[e];
    float4 sh = ((const float4*)esh)[e];
    float4 ra = ((const float4*)rad)[e * 2];
    float4 rb = ((const float4*)rad)[e * 2 + 1];
    int p = atomicAdd(&g_cursor[r], 1);
    float4* D = g_sedge + p * 4;
    D[0] = make_float4(__int_as_float(s), __int_as_float(r), sh.y, sh.z);
    D[1] = make_float4(sh.w, ra.x, ra.y, ra.z);
    D[2] = make_float4(ra.w, rb.x, rb.y, rb.z);
    D[3] = make_float4(rb.w, 0.f, 0.f, 0.f);
}

// ---------------------------------------------------------------------------
// K5 edge kernel: warp handles 16 receiver-sorted edges.
// Register-resident W_r2 (f32x2 packed, pre-scaled), batched radial MLP,
// register run accumulation, direct reg->RED flush (lane-major g_acc).
// ---------------------------------------------------------------------------
__global__ void __launch_bounds__(256)
edge_kernel(const float* __restrict__ W_r1, const float* __restrict__ W_r2) {
    int t = threadIdx.x, warp = t >> 5, lane = t & 31, j8 = lane & 7;
    int p0 = (blockIdx.x * 8 + warp) * 16;

    const float INV_SQRT8 = 0.3535533905932738f;
    const float SC = INV_SQRT8 * 0.25f;          // radial scale * AVG_NEIGH^-0.5
    const float INV_SQRT3 = 0.5773502691896258f;

    // register-resident W_r2, pre-scaled (SC on all; INV_SQRT3 folded into w_st)
    ull w2p01[8], w2p23[8];
    #pragma unroll
    for (int j = 0; j < 8; j++) {
        w2p01[j] = pk2(__ldg(&W_r2[j * 128 + lane]) * SC,
                       __ldg(&W_r2[j * 128 + 32 + lane]) * SC);
        w2p23[j] = pk2(__ldg(&W_r2[j * 128 + 64 + lane]) * SC,
                       __ldg(&W_r2[j * 128 + 96 + lane]) * SC * INV_SQRT3);
    }
    float W1r[8];
    #pragma unroll
    for (int k = 0; k < 8; k++) W1r[k] = __ldg(&W_r1[k * 8 + j8]);

    // coalesced header load: 16 edges x 4 quads = 64 float4 over 2 registers/lane
    const float4* E = g_sedge + p0 * 4;
    float4 hqA = E[lane];
    float4 hqB = E[32 + lane];

    // batched radial MLP: 4 batches x 4 edges; lane = (e_l, j)
    int el4 = (lane >> 3) * 4;
    float hb[4];
    #pragma unroll
    for (int b = 0; b < 4; b++) {
        const float4 hq = (b < 2) ? hqA : hqB;
        int base = (b & 1) * 16 + el4;
        float pre;
        pre  = W1r[0] * __shfl_sync(0xffffffffu, hq.y, base + 1);
        pre  = fmaf(W1r[1], __shfl_sync(0xffffffffu, hq.z, base + 1), pre);
        pre  = fmaf(W1r[2], __shfl_sync(0xffffffffu, hq.w, base + 1), pre);
        pre  = fmaf(W1r[3], __shfl_sync(0xffffffffu, hq.x, base + 2), pre);
        pre  = fmaf(W1r[4], __shfl_sync(0xffffffffu, hq.y, base + 2), pre);
        pre  = fmaf(W1r[5], __shfl_sync(0xffffffffu, hq.z, base + 2), pre);
        pre  = fmaf(W1r[6], __shfl_sync(0xffffffffu, hq.w, base + 2), pre);
        pre  = fmaf(W1r[7], __shfl_sync(0xffffffffu, hq.x, base + 3), pre);
        hb[b] = silu_f(pre * INV_SQRT8);
    }

    float aS0 = 0.f, aS1 = 0.f;
    float aV0l = 0.f, aV0h = 0.f, aV1l = 0.f, aV1h = 0.f, aV2l = 0.f, aV2h = 0.f;
    int cur = __float_as_int(__shfl_sync(0xffffffffu, hqA.y, 0));

    #pragma unroll
    for (int i = 0; i < 16; i++) {
        const float4 hq = (i < 8) ? hqA : hqB;
        int gl = (i * 4) & 31;
        int r = __float_as_int(__shfl_sync(0xffffffffu, hq.y, gl));
        if (r != cur) {
            float* dst = g_acc + (size_t)cur * 256 + lane * 8;
            asm volatile("red.global.add.v4.f32 [%0], {%1,%2,%3,%4};"
                         :: "l"(dst), "f"(aS0), "f"(aS1), "f"(aV0l), "f"(aV0h) : "memory");
            asm volatile("red.global.add.v4.f32 [%0], {%1,%2,%3,%4};"
                         :: "l"(dst + 4), "f"(aV1l), "f"(aV1h), "f"(aV2l), "f"(aV2h) : "memory");
            aS0 = aS1 = aV0l = aV0h = aV1l = aV1h = aV2l = aV2h = 0.f;
            cur = r;
        }
        int snd = __float_as_int(__shfl_sync(0xffffffffu, hq.x, gl));
        float y0 = __shfl_sync(0xffffffffu, hq.z, gl);
        float y1 = __shfl_sync(0xffffffffu, hq.w, gl);
        float y2 = __shfl_sync(0xffffffffu, hq.x, gl + 1);

        // gather sender up-features early (overlap with w matvec)
        float4 u = __ldg(&((const float4*)g_up)[snd * 32 + lane]);

        // w = h @ W_r2 (packed f32x2)
        ull w01 = 0ull, w23 = 0ull;
        float hbreg = hb[i >> 2];
        int hbase = (i & 3) * 8;
        #pragma unroll
        for (int j = 0; j < 8; j++) {
            float hj = __shfl_sync(0xffffffffu, hbreg, hbase + j);
            ull h2 = pk2(hj, hj);
            w01 = fma2_(h2, w2p01[j], w01);
            w23 = fma2_(h2, w2p23[j], w23);
        }
        float w0, w1, w2, w3;
        upk2(w0, w1, w01);
        upk2(w2, w3, w23);

        float dot = u.y * y0;
        dot = fmaf(u.z, y1, dot);
        dot = fmaf(u.w, y2, dot);
        float sst = u.x * w2;

        aS0  = fmaf(u.x, w0, aS0);
        aS1  = fmaf(dot, w3, aS1);
        aV0l = fmaf(u.y, w1, aV0l);  aV0h = fmaf(sst, y0, aV0h);
        aV1l = fmaf(u.z, w1, aV1l);  aV1h = fmaf(sst, y1, aV1h);
        aV2l = fmaf(u.w, w1, aV2l);  aV2h = fmaf(sst, y2, aV2h);
    }

    float* dst = g_acc + (size_t)cur * 256 + lane * 8;
    asm volatile("red.global.add.v4.f32 [%0], {%1,%2,%3,%4};"
                 :: "l"(dst), "f"(aS0), "f"(aS1), "f"(aV0l), "f"(aV0h) : "memory");
    asm volatile("red.global.add.v4.f32 [%0], {%1,%2,%3,%4};"
                 :: "l"(dst + 4), "f"(aV1l), "f"(aV1h), "f"(aV2l), "f"(aV2h) : "memory");
}

// ---------------------------------------------------------------------------
// K6 down-projection + skip + gating: 4 nodes per warp, __ldg weights,
// f32x2-packed accumulation. Block 128 (4 warps, 16 nodes).
// ---------------------------------------------------------------------------
__global__ void __launch_bounds__(128)
down_kernel(const float* __restrict__ nf,
            const int* __restrict__ species,
            float* __restrict__ out) {
    __shared__ float4 st[4][4][96];   // [warp][node][0:64 columns | 64:96 nf]
    int t = threadIdx.x, warp = t >> 5, lane = t & 31;
    int n0 = blockIdx.x * 16 + warp * 4;

    #pragma unroll
    for (int u = 0; u < 4; u++) {
        int n = n0 + u;
        const float4* a4 = (const float4*)g_acc + (size_t)n * 64;
        float4 qa = a4[lane * 2];
        float4 qb = a4[lane * 2 + 1];
        st[warp][u][lane]      = make_float4(qa.x, qa.z, qb.x, qb.z);  // cols m=lane
        st[warp][u][32 + lane] = make_float4(qa.y, qa.w, qb.y, qb.w);  // cols m=32+lane
        const float* f = nf + (size_t)n * 128;
        st[warp][u][64 + lane] = make_float4(f[lane], f[32 + 3 * lane],
                                             f[33 + 3 * lane], f[34 + 3 * lane]);
    }
    __syncwarp();

    const ull* w2p = (const ull*)g_pDn2;
    ull g01[4] = {0, 0, 0, 0}, gv[4] = {0, 0, 0, 0};
    float g4[4] = {0.f, 0.f, 0.f, 0.f};
    #pragma unroll 4
    for (int m = 0; m < 64; m++) {
        ull w2 = __ldg(&w2p[m * 32 + lane]);
        float wv = __ldg(&g_pDnV[m * 32 + lane]);
        ull wv2 = pk2(wv, wv);
        #pragma unroll
        for (int u = 0; u < 4; u++) {
            float4 b = st[warp][u][m];
            g01[u] = fma2_(pk2(b.x, b.x), w2, g01[u]);
            gv[u]  = fma2_(pk2(b.y, b.z), wv2, gv[u]);
            g4[u]  = fmaf(b.w, wv, g4[u]);
        }
    }

    int sp[4];
    #pragma unroll
    for (int u = 0; u < 4; u++) sp[u] = species[n0 + u];

    ull s01[4] = {0, 0, 0, 0}, sv[4] = {0, 0, 0, 0};
    float s4[4] = {0.f, 0.f, 0.f, 0.f};
    #pragma unroll 4
    for (int m = 0; m < 32; m++) {
        #pragma unroll
        for (int u = 0; u < 4; u++) {
            float4 w = __ldg(&g_pSk[sp[u] * 1024 + m * 32 + lane]);
            float4 c = st[warp][u][64 + m];
            s01[u] = fma2_(pk2(c.x, c.x), pk2(w.x, w.y), s01[u]);
            sv[u]  = fma2_(pk2(c.y, c.z), pk2(w.z, w.z), sv[u]);
            s4[u]  = fmaf(c.w, w.z, s4[u]);
        }
    }

    const float A = 0.5f * 0.125f;                 // 0.5 * (2*MUL)^-0.5
    const float B = 0.5f * 0.17677669529663687f;   // 0.5 * MUL^-0.5

    #pragma unroll
    for (int u = 0; u < 4; u++) {
        float G0, G1, H0, H1, S0, S1, T0, T1;
        upk2(G0, G1, g01[u]);
        upk2(H0, H1, gv[u]);
        upk2(S0, S1, s01[u]);
        upk2(T0, T1, sv[u]);
        G0 = G0 * A + S0 * B;
        G1 = G1 * A + S1 * B;
        H0 = H0 * A + T0 * B;
        H1 = H1 * A + T1 * B;
        float H2 = g4[u] * A + s4[u] * B;
        float feat = silu_f(G0);
        float gate = silu_f(G1);
        float* o = out + (size_t)(n0 + u) * 128;
        o[lane] = feat;
        o[32 + lane * 3 + 0] = H0 * gate;
        o[32 + lane * 3 + 1] = H1 * gate;
        o[32 + lane * 3 + 2] = H2 * gate;
    }
}

// ---------------------------------------------------------------------------
extern "C" void kernel_launch(void* const* d_in, const int* in_sizes, int n_in,
                              void* d_out, int out_size) {
    const float* nf  = (const float*)d_in[0];
    const float* esh = (const float*)d_in[1];
    const float* rad = (const float*)d_in[2];
    const float* Wus = (const float*)d_in[3];
    const float* Wuv = (const float*)d_in[4];
    const float* Wr1 = (const float*)d_in[5];
    const float* Wr2 = (const float*)d_in[6];
    const float* Wds = (const float*)d_in[7];
    const float* Wdv = (const float*)d_in[8];
    const float* Wss = (const float*)d_in[9];
    const float* Wsv = (const float*)d_in[10];
    const int* snd  = (const int*)d_in[11];
    const int* rcv  = (const int*)d_in[12];
    const int* spec = (const int*)d_in[13];
    float* out = (float*)d_out;

    prep_kernel<<<92, 256>>>(Wus, Wuv, Wds, Wdv, Wss, Wsv);
    setup_kernel<<<7168, 256>>>(nf, rcv);
    scan_kernel<<<64, 256>>>();
    scatter_kernel<<<512, 512>>>(rcv, snd, esh, rad);
    edge_kernel<<<2048, 256>>>(Wr1, Wr2);
    down_kernel<<<1024, 128>>>(nf, spec, out);
}